// round 16
// baseline (speedup 1.0000x reference)
#include <cuda_runtime.h>
#include <cuda_fp16.h>
#include <cstdint>

#define NN 20000
#define NE 320000
#define FF 64
#define RR 8
#define HH 64
#define PP 5
#define SS 10
#define TILE 64
#define NTILES (NE / TILE)
#define NBC 60

#define INV_SQRT3 0.5773502691896258f
#define INV_SQRT2 0.7071067811865476f

// scratch (static __device__ — no allocations allowed)
__device__ float g_s1[NN * FF];
__device__ float g_v1[NN * FF * 3];
__device__ float g_As[NN * FF];
__device__ float g_Av[NN * FF * 3];
__device__ int g_cur[16];
__device__ int g_order[SS * NN];
// receiver-sort scratch
__device__ int g_rcnt[NN];
__device__ int g_rcur[NN];
__device__ int g_roff[NN];
__device__ int g_eorder[NE];

// ---------------------------------------------------------------------------
__device__ __forceinline__ void red4(float* addr, float a, float b, float c, float d) {
    asm volatile("red.global.add.v4.f32 [%0], {%1,%2,%3,%4};"
                 :: "l"(__cvta_generic_to_global(addr)),
                    "f"(a), "f"(b), "f"(c), "f"(d) : "memory");
}
__device__ __forceinline__ void ldsm_x4(uint32_t* r, uint32_t addr) {
    asm volatile("ldmatrix.sync.aligned.m8n8.x4.shared.b16 {%0,%1,%2,%3}, [%4];"
                 : "=r"(r[0]), "=r"(r[1]), "=r"(r[2]), "=r"(r[3]) : "r"(addr));
}
__device__ __forceinline__ void ldsm_x4t(uint32_t* r, uint32_t addr) {
    asm volatile("ldmatrix.sync.aligned.m8n8.x4.trans.shared.b16 {%0,%1,%2,%3}, [%4];"
                 : "=r"(r[0]), "=r"(r[1]), "=r"(r[2]), "=r"(r[3]) : "r"(addr));
}
__device__ __forceinline__ void mma_f16(float* c, const uint32_t* a, const uint32_t* b) {
    asm volatile("mma.sync.aligned.m16n8k16.row.col.f32.f16.f16.f32 "
                 "{%0,%1,%2,%3}, {%4,%5,%6,%7}, {%8,%9}, {%0,%1,%2,%3};"
                 : "+f"(c[0]), "+f"(c[1]), "+f"(c[2]), "+f"(c[3])
                 : "r"(a[0]), "r"(a[1]), "r"(a[2]), "r"(a[3]),
                   "r"(b[0]), "r"(b[1]));
}
__device__ __forceinline__ uint32_t smem_u32(const void* p) {
    uint32_t a;
    asm("{ .reg .u64 t; cvta.to.shared.u64 t, %1; cvt.u32.u64 %0, t; }"
        : "=r"(a) : "l"(p));
    return a;
}

// smem layout for kedge: W1 + B hi/lo (fp16) + double-buffered fp16 A
#define ASTRIDE 72
#define BSTRIDE 328
#define OFF_W1   0
#define OFF_BHI  2048
#define OFF_BLO  (OFF_BHI + 41984)
#define OFF_A    (OFF_BLO + 41984)
#define ABUF_SZ  9216
#define DYN_BYTES (OFF_A + 2 * ABUF_SZ)  // 104448 B

// ---------------------------------------------------------------------------
__global__ void kreset() {
    int i = blockIdx.x * blockDim.x + threadIdx.x;
    if (i < 16) g_cur[i] = 0;
    for (int k = i; k < NN; k += gridDim.x * blockDim.x) {
        g_rcnt[k] = 0;
        g_rcur[k] = 0;
    }
}
__global__ void khist2(const int* __restrict__ rcv) {
    int e = blockIdx.x * blockDim.x + threadIdx.x;
    if (e < NE) atomicAdd(&g_rcnt[rcv[e]], 1);
}
__global__ __launch_bounds__(512) void kscan2() {
    __shared__ int part[512];
    int tid = threadIdx.x;
    int base = tid * 40;
    int sum = 0;
    for (int k = 0; k < 40; k++) {
        int b = base + k;
        sum += (b < NN) ? g_rcnt[b] : 0;
    }
    part[tid] = sum;
    __syncthreads();
    for (int d = 1; d < 512; d <<= 1) {
        int vv = (tid >= d) ? part[tid - d] : 0;
        __syncthreads();
        part[tid] += vv;
        __syncthreads();
    }
    int run = (tid > 0) ? part[tid - 1] : 0;
    for (int k = 0; k < 40; k++) {
        int b = base + k;
        if (b < NN) { g_roff[b] = run; run += g_rcnt[b]; }
    }
}
__global__ void kscat2(const int* __restrict__ rcv) {
    int e = blockIdx.x * blockDim.x + threadIdx.x;
    if (e < NE) {
        int r = rcv[e];
        int pos = g_roff[r] + atomicAdd(&g_rcur[r], 1);
        g_eorder[pos] = e;
    }
}

// ---------------------------------------------------------------------------
// Kernel A: s1/v1 linear-up, zero accumulators, fused species binning.
// ---------------------------------------------------------------------------
__global__ __launch_bounds__(256) void knodeA(
    const float* __restrict__ s, const float* __restrict__ v,
    const int* __restrict__ spec,
    const float* __restrict__ Wls, const float* __restrict__ Wlv)
{
    __shared__ float sWls[FF * FF], sWlv[FF * FF];
    __shared__ float sS[4 * FF], sV[4 * FF * 3];
    for (int i = threadIdx.x; i < FF * FF; i += blockDim.x) {
        sWls[i] = Wls[i];
        sWlv[i] = Wlv[i];
    }
    const int ngrp = NN / 4;
    for (int grp = blockIdx.x; grp < ngrp; grp += gridDim.x) {
        __syncthreads();
        int nbase = grp * 4;
        for (int i = threadIdx.x; i < 4 * FF; i += blockDim.x)
            sS[i] = s[nbase * FF + i];
        for (int i = threadIdx.x; i < 4 * FF * 3; i += blockDim.x)
            sV[i] = v[nbase * FF * 3 + i];
        __syncthreads();
        int nl = threadIdx.x >> 6, g = threadIdx.x & 63;
        int n = nbase + nl;
        if (g == 0) {
            int sp = spec[n];
            int pos = atomicAdd(&g_cur[sp], 1);
            g_order[sp * NN + pos] = n;
        }
        const float* ps = sS + nl * FF;
        const float* pv = sV + nl * FF * 3;
        float as = 0.f, ax = 0.f, ay = 0.f, az = 0.f;
#pragma unroll 8
        for (int f = 0; f < FF; f++) {
            float wls = sWls[f * FF + g], wlv = sWlv[f * FF + g];
            as += ps[f] * wls;
            ax += pv[f * 3 + 0] * wlv;
            ay += pv[f * 3 + 1] * wlv;
            az += pv[f * 3 + 2] * wlv;
        }
        g_s1[n * FF + g] = as;
        g_v1[n * FF * 3 + g * 3 + 0] = ax;
        g_v1[n * FF * 3 + g * 3 + 1] = ay;
        g_v1[n * FF * 3 + g * 3 + 2] = az;
        g_As[n * FF + g] = 0.f;
        g_Av[n * FF * 3 + g * 3 + 0] = 0.f;
        g_Av[n * FF * 3 + g * 3 + 1] = 0.f;
        g_Av[n * FF * 3 + g * 3 + 2] = 0.f;
    }
}

// ---------------------------------------------------------------------------
// Kernel B: fp16 2-pass GEMM over RECEIVER-SORTED edges (via g_eorder) with
// warp-level segmented pre-combination of scatter messages: 8 consecutive
// sorted edges per (ms,eidx) group share 1-2 receivers -> only segment heads
// issue red4 (op count /~6). Register-direct epilogue (W2 col permutation).
// ---------------------------------------------------------------------------
__global__ __launch_bounds__(256, 1) void kedge10(
    const float* __restrict__ Y1, const float* __restrict__ efg,
    const int* __restrict__ senders, const int* __restrict__ receivers,
    const float* __restrict__ W_rad1, const float* __restrict__ W_rad2)
{
    extern __shared__ char dsm[];
    float* sW1 = (float*)(dsm + OFF_W1);
    const uint32_t uBhi = smem_u32(dsm + OFF_BHI);
    const uint32_t uBlo = smem_u32(dsm + OFF_BLO);
    const uint32_t uA0 = smem_u32(dsm + OFF_A);

    const int tid = threadIdx.x, wid = tid >> 5, lane = tid & 31;

    for (int i = tid; i < RR * HH; i += 256) {
        int r = i / HH, j = i % HH;
        sW1[j * RR + r] = W_rad1[i];
    }
    // W2 -> B hi/lo fp16, column-PERMUTED within each 16-col group
    for (int i = tid; i < HH * (PP * FF / 2); i += 256) {
        int k = i / 160, n2 = i % 160;
        int grp = n2 >> 3, m = n2 & 7;
        int sc = grp * 16 + (m & 1) * 8 + ((m >> 1) << 1);
        float w0 = W_rad2[k * (PP * FF) + 2 * n2];
        float w1 = W_rad2[k * (PP * FF) + 2 * n2 + 1];
        __half h0 = __float2half(w0);
        __half h1 = __float2half(w1);
        __half l0 = __float2half(w0 - __half2float(h0));
        __half l1 = __float2half(w1 - __half2float(h1));
        uint32_t off = (uint32_t)(k * BSTRIDE + sc) * 2;
        __half2 ph; ph.x = h0; ph.y = h1;
        __half2 pl; pl.x = l0; pl.y = l1;
        *(__half2*)(dsm + OFF_BHI + off) = ph;
        *(__half2*)(dsm + OFF_BLO + off) = pl;
    }

    const int em = wid & 1;        // edge half (32 edges)
    const int cn = wid >> 1;       // 16-col quarter within each path
    const int lm = lane >> 3, lr = lane & 7;
    const int arow0 = em * 32 + (lm & 1) * 8 + lr;
    const int acol0 = (lm >> 1) * 8;
    const int brow0 = (lm & 1) * 8 + lr;
    const int qq = lane & 3, eh = lane >> 2;

    auto stageA = [&](int t, int buf) {
        char* ab = dsm + OFF_A + buf * ABUF_SZ;
        int e = tid & 63, jq = tid >> 6;
        int eo = __ldg(g_eorder + t * TILE + e);
        const float4* efp = (const float4*)(efg + (size_t)eo * RR);
        float4 F0 = efp[0], F1 = efp[1];
#pragma unroll
        for (int jj = 0; jj < 16; jj += 2) {
            int j = jq * 16 + jj;
            const float4* wA = (const float4*)(sW1 + j * RR);
            float4 a0 = wA[0], a1 = wA[1], b0 = wA[2], b1 = wA[3];
            float z0 = F0.x * a0.x + F0.y * a0.y + F0.z * a0.z + F0.w * a0.w +
                       F1.x * a1.x + F1.y * a1.y + F1.z * a1.z + F1.w * a1.w;
            float z1 = F0.x * b0.x + F0.y * b0.y + F0.z * b0.z + F0.w * b0.w +
                       F1.x * b1.x + F1.y * b1.y + F1.z * b1.z + F1.w * b1.w;
            float h0f = __fdividef(z0, 1.f + __expf(-z0));
            float h1f = __fdividef(z1, 1.f + __expf(-z1));
            __half2 ph; ph.x = __float2half(h0f); ph.y = __float2half(h1f);
            *(__half2*)(ab + (uint32_t)(e * ASTRIDE + j) * 2) = ph;
        }
    };

    const int t0 = blockIdx.x;
    if (t0 < NTILES) stageA(t0, 0);
    __syncthreads();

    int it = 0;
    for (int t = t0; t < NTILES; t += gridDim.x, it++) {
        const int buf = it & 1;
        const uint32_t uA = uA0 + buf * ABUF_SZ;

        // ---- GEMM: acc[p][msub][nt][4]; cols = p*64 + cn*16; 2 fp16 passes --
        float acc[PP][2][2][4];
#pragma unroll
        for (int p = 0; p < PP; p++)
#pragma unroll
            for (int ms = 0; ms < 2; ms++)
#pragma unroll
                for (int nt = 0; nt < 2; nt++) {
                    acc[p][ms][nt][0] = 0.f; acc[p][ms][nt][1] = 0.f;
                    acc[p][ms][nt][2] = 0.f; acc[p][ms][nt][3] = 0.f;
                }
#pragma unroll
        for (int pass = 0; pass < 2; pass++) {
            uint32_t Bb = (pass == 1) ? uBlo : uBhi;
#pragma unroll
            for (int k = 0; k < 4; k++) {
                uint32_t a0[4], a1[4];
                ldsm_x4(a0, uA + (uint32_t)(arow0 * ASTRIDE + k * 16 + acol0) * 2);
                ldsm_x4(a1, uA + (uint32_t)((arow0 + 16) * ASTRIDE + k * 16 + acol0) * 2);
#pragma unroll
                for (int p = 0; p < PP; p++) {
                    int col = p * 64 + cn * 16;
                    uint32_t b[4];
                    ldsm_x4t(b, Bb + (uint32_t)((k * 16 + brow0) * BSTRIDE +
                                                col + acol0) * 2);
                    mma_f16(acc[p][0][0], a0, b);
                    mma_f16(acc[p][0][1], a0, b + 2);
                    mma_f16(acc[p][1][0], a1, b);
                    mma_f16(acc[p][1][1], a1, b + 2);
                }
            }
        }

        int tn = t + gridDim.x;
        if (tn < NTILES) stageA(tn, buf ^ 1);

        // ---- epilogue: TP per edge, then segmented combine over 8 sorted
        //      edges (lane stride 4), heads issue red4 ----
        const int f = cn * 16 + 4 * qq;
#pragma unroll
        for (int ms = 0; ms < 2; ms++) {
#pragma unroll
            for (int eidx = 0; eidx < 2; eidx++) {
                int sl = t * TILE + em * 32 + ms * 16 + eidx * 8 + eh;
                int eo = __ldg(g_eorder + sl);
                int snd = senders[eo], rcv = receivers[eo];
                float Yx = Y1[eo * 3 + 0], Yy = Y1[eo * 3 + 1], Yz = Y1[eo * 3 + 2];
                const float* sp = g_s1 + (size_t)snd * FF;
                const float* vp = g_v1 + (size_t)snd * FF * 3;

                float4 ss = *(const float4*)(sp + f);
                const float* vq = vp + f * 3;
                float4 va = *(const float4*)(vq + 0);
                float4 vb = *(const float4*)(vq + 4);
                float4 vc = *(const float4*)(vq + 8);
                float ssf[4] = {ss.x, ss.y, ss.z, ss.w};
                float vx[4] = {va.x, va.w, vb.z, vc.y};
                float vy[4] = {va.y, vb.x, vb.w, vc.z};
                float vz[4] = {va.z, vb.y, vc.x, vc.w};
                float vals[16];
#pragma unroll
                for (int j = 0; j < 4; j++) {
                    int nt = j >> 1, cb = j & 1;
                    float tw0 = acc[0][ms][nt][eidx * 2 + cb];
                    float tw1 = acc[1][ms][nt][eidx * 2 + cb];
                    float tw2 = acc[2][ms][nt][eidx * 2 + cb];
                    float tw3 = acc[3][ms][nt][eidx * 2 + cb];
                    float tw4 = acc[4][ms][nt][eidx * 2 + cb];
                    float dot = vx[j] * Yx + vy[j] * Yy + vz[j] * Yz;
                    float cx = vy[j] * Yz - vz[j] * Yy;
                    float cy = vz[j] * Yx - vx[j] * Yz;
                    float cz = vx[j] * Yy - vy[j] * Yx;
                    vals[j] = tw0 * ssf[j] + tw1 * dot * INV_SQRT3;
                    float t2s = tw2 * ssf[j];
                    float t4 = tw4 * INV_SQRT2;
                    vals[4 + 3 * j + 0] = t2s * Yx + tw3 * vx[j] + t4 * cx;
                    vals[4 + 3 * j + 1] = t2s * Yy + tw3 * vy[j] + t4 * cy;
                    vals[4 + 3 * j + 2] = t2s * Yz + tw3 * vz[j] + t4 * cz;
                }
                // segmented sum toward lowest-eh lane of each equal-rcv run
#pragma unroll
                for (int d = 1; d < 8; d <<= 1) {
                    int orcv = __shfl_down_sync(0xffffffffu, rcv, 4 * d);
                    bool ok = (eh + d < 8) && (orcv == rcv);
#pragma unroll
                    for (int q2 = 0; q2 < 16; q2++) {
                        float tv = __shfl_down_sync(0xffffffffu, vals[q2], 4 * d);
                        if (ok) vals[q2] += tv;
                    }
                }
                int prcv = __shfl_up_sync(0xffffffffu, rcv, 4);
                if (eh == 0 || prcv != rcv) {
                    float* Ap = g_As + (size_t)rcv * FF;
                    float* Vp = g_Av + (size_t)rcv * FF * 3;
                    red4(Ap + f, vals[0], vals[1], vals[2], vals[3]);
                    float* wq = Vp + f * 3;
                    red4(wq + 0, vals[4], vals[5], vals[6], vals[7]);
                    red4(wq + 4, vals[8], vals[9], vals[10], vals[11]);
                    red4(wq + 8, vals[12], vals[13], vals[14], vals[15]);
                }
            }
        }
        __syncthreads();
    }
}

// ---------------------------------------------------------------------------
// Kernel C (R15 best): species-binned, 8 nodes/iter (2 per thread), W_sc in
// smem (float2), W_int/W_prod via __ldg broadcast, float4-packed node staging.
// ---------------------------------------------------------------------------
__global__ __launch_bounds__(256) void knodeC(
    const float* __restrict__ s, const float* __restrict__ v,
    const float* __restrict__ W_sc_s, const float* __restrict__ W_sc_v,
    const float* __restrict__ W_int_s, const float* __restrict__ W_int_v,
    const float* __restrict__ w_prod_s, const float* __restrict__ w_prod_v,
    const float* __restrict__ W_prod_s, const float* __restrict__ W_prod_v,
    const float* __restrict__ W_read,
    float* __restrict__ out_node, float* __restrict__ out_s,
    float* __restrict__ out_v)
{
    __shared__ float2 sWsc[FF * FF];
    __shared__ float swps[5 * FF], swpv[4 * FF], sWr[FF];
    __shared__ float4 sAX[8 * FF];
    __shared__ float4 sVX[8 * FF];
    __shared__ float4 sBX[8 * FF];
    __shared__ float sRed[16];
    __shared__ int sNode[8];

    const int sp = blockIdx.x / NBC;
    const int chunk = blockIdx.x % NBC;
    const int cnt = g_cur[sp];
    const int tid = threadIdx.x;

    for (int i = tid; i < FF * FF; i += 256)
        sWsc[i] = make_float2(W_sc_s[sp * FF * FF + i], W_sc_v[sp * FF * FF + i]);
    if (tid < FF) sWr[tid] = W_read[tid];
    for (int i = tid; i < 5 * FF; i += 256) swps[i] = w_prod_s[sp * 5 * FF + i];
    if (tid < 4 * FF) swpv[tid] = w_prod_v[sp * 4 * FF + tid];

    const int* order = g_order + sp * NN;

    for (int gbase = chunk * 8; gbase < cnt; gbase += NBC * 8) {
        __syncthreads();
        if (tid < 8) {
            int idx = gbase + tid;
            sNode[tid] = (idx < cnt) ? order[idx] : -1;
        }
        __syncthreads();
        for (int i = tid; i < 8 * FF; i += 256) {
            int node = sNode[i >> 6];
            if (node < 0) node = sNode[0];
            int f = i & 63;
            const float* avp = g_Av + (size_t)node * FF * 3 + f * 3;
            const float* vvp = v + (size_t)node * FF * 3 + f * 3;
            sAX[i] = make_float4(avp[0], avp[1], avp[2], g_As[(size_t)node * FF + f]);
            sVX[i] = make_float4(vvp[0], vvp[1], vvp[2], s[(size_t)node * FF + f]);
        }
        __syncthreads();

        int nl = tid >> 6, g = tid & 63;
        int n0 = sNode[nl], n1 = sNode[nl + 4];
        const float4* pA0 = sAX + nl * FF;
        const float4* pX0 = sVX + nl * FF;
        const float4* pA1 = sAX + (nl + 4) * FF;
        const float4* pX1 = sVX + (nl + 4) * FF;

        float as0 = 0.f, ax0 = 0.f, ay0 = 0.f, az0 = 0.f;
        float cs0 = 0.f, cx0 = 0.f, cy0 = 0.f, cz0 = 0.f;
        float as1 = 0.f, ax1 = 0.f, ay1 = 0.f, az1 = 0.f;
        float cs1 = 0.f, cx1 = 0.f, cy1 = 0.f, cz1 = 0.f;
#pragma unroll 4
        for (int f = 0; f < FF; f++) {
            float wis = __ldg(W_int_s + f * FF + g);
            float wiv = __ldg(W_int_v + f * FF + g);
            float2 wsc = sWsc[f * FF + g];
            float4 a0 = pA0[f], x0 = pX0[f];
            float4 a1 = pA1[f], x1 = pX1[f];
            as0 += a0.w * wis;
            ax0 += a0.x * wiv; ay0 += a0.y * wiv; az0 += a0.z * wiv;
            cs0 += x0.w * wsc.x;
            cx0 += x0.x * wsc.y; cy0 += x0.y * wsc.y; cz0 += x0.z * wsc.y;
            as1 += a1.w * wis;
            ax1 += a1.x * wiv; ay1 += a1.y * wiv; az1 += a1.z * wiv;
            cs1 += x1.w * wsc.x;
            cx1 += x1.x * wsc.y; cy1 += x1.y * wsc.y; cz1 += x1.z * wsc.y;
        }
        const float inv = 0.25f;
        as0 *= inv; ax0 *= inv; ay0 *= inv; az0 *= inv;
        as1 *= inv; ax1 *= inv; ay1 *= inv; az1 *= inv;

        float w0 = swps[0 * FF + g], w1 = swps[1 * FF + g], w2 = swps[2 * FF + g];
        float w3 = swps[3 * FF + g], w4 = swps[4 * FF + g];
        float u0 = swpv[0 * FF + g], u1 = swpv[1 * FF + g];
        float u2 = swpv[2 * FF + g], u3 = swpv[3 * FF + g];
        {
            float d = ax0 * ax0 + ay0 * ay0 + az0 * az0;
            float a2 = as0 * as0;
            float Bs = w0 * as0 + w1 * a2 + w2 * d + w3 * a2 * as0 + w4 * as0 * d;
            float gv = u0 + u1 * as0 + u2 * a2 + u3 * d;
            sBX[nl * FF + g] = make_float4(gv * ax0, gv * ay0, gv * az0, Bs);
        }
        {
            float d = ax1 * ax1 + ay1 * ay1 + az1 * az1;
            float a2 = as1 * as1;
            float Bs = w0 * as1 + w1 * a2 + w2 * d + w3 * a2 * as1 + w4 * as1 * d;
            float gv = u0 + u1 * as1 + u2 * a2 + u3 * d;
            sBX[(nl + 4) * FF + g] = make_float4(gv * ax1, gv * ay1, gv * az1, Bs);
        }
        __syncthreads();

        const float4* pB0 = sBX + nl * FF;
        const float4* pB1 = sBX + (nl + 4) * FF;
        float so0 = cs0, vx0 = cx0, vy0 = cy0, vz0 = cz0;
        float so1 = cs1, vx1 = cx1, vy1 = cy1, vz1 = cz1;
#pragma unroll 4
        for (int f = 0; f < FF; f++) {
            float wp = __ldg(W_prod_s + f * FF + g);
            float wv = __ldg(W_prod_v + f * FF + g);
            float4 b0 = pB0[f], b1 = pB1[f];
            so0 += b0.w * wp;
            vx0 += b0.x * wv; vy0 += b0.y * wv; vz0 += b0.z * wv;
            so1 += b1.w * wp;
            vx1 += b1.x * wv; vy1 += b1.y * wv; vz1 += b1.z * wv;
        }
        if (n0 >= 0) {
            out_s[n0 * FF + g] = so0;
            out_v[n0 * FF * 3 + g * 3 + 0] = vx0;
            out_v[n0 * FF * 3 + g * 3 + 1] = vy0;
            out_v[n0 * FF * 3 + g * 3 + 2] = vz0;
        }
        if (n1 >= 0) {
            out_s[n1 * FF + g] = so1;
            out_v[n1 * FF * 3 + g * 3 + 0] = vx1;
            out_v[n1 * FF * 3 + g * 3 + 1] = vy1;
            out_v[n1 * FF * 3 + g * 3 + 2] = vz1;
        }

        float r0 = so0 * sWr[g];
        float r1 = so1 * sWr[g];
#pragma unroll
        for (int o = 16; o > 0; o >>= 1) {
            r0 += __shfl_down_sync(0xffffffffu, r0, o);
            r1 += __shfl_down_sync(0xffffffffu, r1, o);
        }
        int w = tid >> 5;
        if ((tid & 31) == 0) { sRed[w * 2] = r0; sRed[w * 2 + 1] = r1; }
        __syncthreads();
        if (tid < 8) {
            int base = (tid & 3) * 4;
            if (tid < 4) {
                int n = sNode[tid];
                if (n >= 0) out_node[n] = sRed[base] + sRed[base + 2];
            } else {
                int n = sNode[(tid & 3) + 4];
                if (n >= 0) out_node[n] = sRed[base + 1] + sRed[base + 3];
            }
        }
    }
}

// ---------------------------------------------------------------------------
extern "C" void kernel_launch(void* const* d_in, const int* in_sizes, int n_in,
                              void* d_out, int out_size)
{
    const float* s    = (const float*)d_in[0];
    const float* v    = (const float*)d_in[1];
    const float* Y1   = (const float*)d_in[2];
    const float* ef   = (const float*)d_in[3];
    const int*   spec = (const int*)d_in[4];
    const int*   snd  = (const int*)d_in[5];
    const int*   rcv  = (const int*)d_in[6];
    const float* Wls  = (const float*)d_in[7];
    const float* Wlv  = (const float*)d_in[8];
    const float* Wscs = (const float*)d_in[9];
    const float* Wscv = (const float*)d_in[10];
    const float* Wr1  = (const float*)d_in[11];
    const float* Wr2  = (const float*)d_in[12];
    const float* Wis  = (const float*)d_in[13];
    const float* Wiv  = (const float*)d_in[14];
    const float* wps  = (const float*)d_in[15];
    const float* wpv  = (const float*)d_in[16];
    const float* Wps  = (const float*)d_in[17];
    const float* Wpv  = (const float*)d_in[18];
    const float* Wrd  = (const float*)d_in[19];

    float* out = (float*)d_out;
    float* out_node = out;
    float* out_s = out + NN;
    float* out_v = out + NN + NN * FF;

    cudaFuncSetAttribute(kedge10, cudaFuncAttributeMaxDynamicSharedMemorySize, DYN_BYTES);

    kreset<<<160, 256>>>();
    khist2<<<(NE + 255) / 256, 256>>>(rcv);
    kscan2<<<1, 512>>>();
    kscat2<<<(NE + 255) / 256, 256>>>(rcv);
    knodeA<<<592, 256>>>(s, v, spec, Wls, Wlv);
    kedge10<<<152, 256, DYN_BYTES>>>(Y1, ef, snd, rcv, Wr1, Wr2);
    knodeC<<<SS * NBC, 256>>>(s, v, Wscs, Wscv, Wis, Wiv,
                              wps, wpv, Wps, Wpv, Wrd,
                              out_node, out_s, out_v);
}

// round 17
// speedup vs baseline: 1.1961x; 1.1961x over previous
#include <cuda_runtime.h>
#include <cuda_fp16.h>
#include <cstdint>

#define NN 20000
#define NE 320000
#define FF 64
#define RR 8
#define HH 64
#define PP 5
#define SS 10
#define TILE 64
#define NTILES (NE / TILE)
#define NBC 60

#define INV_SQRT3 0.5773502691896258f
#define INV_SQRT2 0.7071067811865476f

// scratch (static __device__ — no allocations allowed); planar layouts
__device__ float g_s1[NN * FF];
__device__ float g_v1x[NN * FF];
__device__ float g_v1y[NN * FF];
__device__ float g_v1z[NN * FF];
__device__ float g_As[NN * FF];
__device__ float g_Avx[NN * FF];
__device__ float g_Avy[NN * FF];
__device__ float g_Avz[NN * FF];
__device__ int g_cur[16];
__device__ int g_order[SS * NN];

// ---------------------------------------------------------------------------
__device__ __forceinline__ void red4(float* addr, float a, float b, float c, float d) {
    asm volatile("red.global.add.v4.f32 [%0], {%1,%2,%3,%4};"
                 :: "l"(__cvta_generic_to_global(addr)),
                    "f"(a), "f"(b), "f"(c), "f"(d) : "memory");
}
__device__ __forceinline__ void ldsm_x4(uint32_t* r, uint32_t addr) {
    asm volatile("ldmatrix.sync.aligned.m8n8.x4.shared.b16 {%0,%1,%2,%3}, [%4];"
                 : "=r"(r[0]), "=r"(r[1]), "=r"(r[2]), "=r"(r[3]) : "r"(addr));
}
__device__ __forceinline__ void ldsm_x4t(uint32_t* r, uint32_t addr) {
    asm volatile("ldmatrix.sync.aligned.m8n8.x4.trans.shared.b16 {%0,%1,%2,%3}, [%4];"
                 : "=r"(r[0]), "=r"(r[1]), "=r"(r[2]), "=r"(r[3]) : "r"(addr));
}
__device__ __forceinline__ void mma_f16(float* c, const uint32_t* a, const uint32_t* b) {
    asm volatile("mma.sync.aligned.m16n8k16.row.col.f32.f16.f16.f32 "
                 "{%0,%1,%2,%3}, {%4,%5,%6,%7}, {%8,%9}, {%0,%1,%2,%3};"
                 : "+f"(c[0]), "+f"(c[1]), "+f"(c[2]), "+f"(c[3])
                 : "r"(a[0]), "r"(a[1]), "r"(a[2]), "r"(a[3]),
                   "r"(b[0]), "r"(b[1]));
}
__device__ __forceinline__ uint32_t smem_u32(const void* p) {
    uint32_t a;
    asm("{ .reg .u64 t; cvta.to.shared.u64 t, %1; cvt.u32.u64 %0, t; }"
        : "=r"(a) : "l"(p));
    return a;
}

// smem layout for kedge: W1 + B hi/lo (fp16) + double-buffered fp16 A
#define ASTRIDE 72
#define BSTRIDE 328
#define OFF_W1   0
#define OFF_BHI  2048
#define OFF_BLO  (OFF_BHI + 41984)
#define OFF_A    (OFF_BLO + 41984)
#define ABUF_SZ  9216
#define DYN_BYTES (OFF_A + 2 * ABUF_SZ)  // 104448 B

// ---------------------------------------------------------------------------
__global__ void kreset() {
    if (threadIdx.x < 16) g_cur[threadIdx.x] = 0;
}

// ---------------------------------------------------------------------------
// Kernel A: s1/v1 linear-up (planar outputs, fully coalesced stores),
// zero accumulators, fused species binning.
// ---------------------------------------------------------------------------
__global__ __launch_bounds__(256) void knodeA(
    const float* __restrict__ s, const float* __restrict__ v,
    const int* __restrict__ spec,
    const float* __restrict__ Wls, const float* __restrict__ Wlv)
{
    __shared__ float sWls[FF * FF], sWlv[FF * FF];
    __shared__ float sS[4 * FF], sV[4 * FF * 3];
    for (int i = threadIdx.x; i < FF * FF; i += blockDim.x) {
        sWls[i] = Wls[i];
        sWlv[i] = Wlv[i];
    }
    const int ngrp = NN / 4;
    for (int grp = blockIdx.x; grp < ngrp; grp += gridDim.x) {
        __syncthreads();
        int nbase = grp * 4;
        for (int i = threadIdx.x; i < 4 * FF; i += blockDim.x)
            sS[i] = s[nbase * FF + i];
        for (int i = threadIdx.x; i < 4 * FF * 3; i += blockDim.x)
            sV[i] = v[nbase * FF * 3 + i];
        __syncthreads();
        int nl = threadIdx.x >> 6, g = threadIdx.x & 63;
        int n = nbase + nl;
        if (g == 0) {
            int sp = spec[n];
            int pos = atomicAdd(&g_cur[sp], 1);
            g_order[sp * NN + pos] = n;
        }
        const float* ps = sS + nl * FF;
        const float* pv = sV + nl * FF * 3;
        float as = 0.f, ax = 0.f, ay = 0.f, az = 0.f;
#pragma unroll 8
        for (int f = 0; f < FF; f++) {
            float wls = sWls[f * FF + g], wlv = sWlv[f * FF + g];
            as += ps[f] * wls;
            ax += pv[f * 3 + 0] * wlv;
            ay += pv[f * 3 + 1] * wlv;
            az += pv[f * 3 + 2] * wlv;
        }
        int o = n * FF + g;
        g_s1[o] = as;
        g_v1x[o] = ax;
        g_v1y[o] = ay;
        g_v1z[o] = az;
        g_As[o] = 0.f;
        g_Avx[o] = 0.f;
        g_Avy[o] = 0.f;
        g_Avz[o] = 0.f;
    }
}

// ---------------------------------------------------------------------------
// Kernel B (R15 best + planar gathers/scatters): fp16 2-pass GEMM
// (W exact hi/lo, h quantized once), edge-half x col-quarter warp layout,
// register-direct red.v4 epilogue via W2 column permutation.
// ---------------------------------------------------------------------------
__global__ __launch_bounds__(256, 1) void kedge9(
    const float* __restrict__ Y1, const float* __restrict__ efg,
    const int* __restrict__ senders, const int* __restrict__ receivers,
    const float* __restrict__ W_rad1, const float* __restrict__ W_rad2)
{
    extern __shared__ char dsm[];
    float* sW1 = (float*)(dsm + OFF_W1);
    const uint32_t uBhi = smem_u32(dsm + OFF_BHI);
    const uint32_t uBlo = smem_u32(dsm + OFF_BLO);
    const uint32_t uA0 = smem_u32(dsm + OFF_A);

    const int tid = threadIdx.x, wid = tid >> 5, lane = tid & 31;

    for (int i = tid; i < RR * HH; i += 256) {
        int r = i / HH, j = i % HH;
        sW1[j * RR + r] = W_rad1[i];
    }
    // W2 -> B hi/lo fp16, column-PERMUTED within each 16-col group
    for (int i = tid; i < HH * (PP * FF / 2); i += 256) {
        int k = i / 160, n2 = i % 160;
        int grp = n2 >> 3, m = n2 & 7;
        int sc = grp * 16 + (m & 1) * 8 + ((m >> 1) << 1);
        float w0 = W_rad2[k * (PP * FF) + 2 * n2];
        float w1 = W_rad2[k * (PP * FF) + 2 * n2 + 1];
        __half h0 = __float2half(w0);
        __half h1 = __float2half(w1);
        __half l0 = __float2half(w0 - __half2float(h0));
        __half l1 = __float2half(w1 - __half2float(h1));
        uint32_t off = (uint32_t)(k * BSTRIDE + sc) * 2;
        __half2 ph; ph.x = h0; ph.y = h1;
        __half2 pl; pl.x = l0; pl.y = l1;
        *(__half2*)(dsm + OFF_BHI + off) = ph;
        *(__half2*)(dsm + OFF_BLO + off) = pl;
    }

    const int em = wid & 1;        // edge half (32 edges)
    const int cn = wid >> 1;       // 16-col quarter within each path
    const int lm = lane >> 3, lr = lane & 7;
    const int arow0 = em * 32 + (lm & 1) * 8 + lr;
    const int acol0 = (lm >> 1) * 8;
    const int brow0 = (lm & 1) * 8 + lr;
    const int qq = lane & 3, eh = lane >> 2;

    auto stageA = [&](int t, int buf) {
        char* ab = dsm + OFF_A + buf * ABUF_SZ;
        int e = tid & 63, jq = tid >> 6;
        const float4* efp = (const float4*)(efg + (size_t)(t * TILE + e) * RR);
        float4 F0 = efp[0], F1 = efp[1];
#pragma unroll
        for (int jj = 0; jj < 16; jj += 2) {
            int j = jq * 16 + jj;
            const float4* wA = (const float4*)(sW1 + j * RR);
            float4 a0 = wA[0], a1 = wA[1], b0 = wA[2], b1 = wA[3];
            float z0 = F0.x * a0.x + F0.y * a0.y + F0.z * a0.z + F0.w * a0.w +
                       F1.x * a1.x + F1.y * a1.y + F1.z * a1.z + F1.w * a1.w;
            float z1 = F0.x * b0.x + F0.y * b0.y + F0.z * b0.z + F0.w * b0.w +
                       F1.x * b1.x + F1.y * b1.y + F1.z * b1.z + F1.w * b1.w;
            float h0f = __fdividef(z0, 1.f + __expf(-z0));
            float h1f = __fdividef(z1, 1.f + __expf(-z1));
            __half2 ph; ph.x = __float2half(h0f); ph.y = __float2half(h1f);
            *(__half2*)(ab + (uint32_t)(e * ASTRIDE + j) * 2) = ph;
        }
    };

    const int t0 = blockIdx.x;
    if (t0 < NTILES) stageA(t0, 0);
    __syncthreads();

    int it = 0;
    for (int t = t0; t < NTILES; t += gridDim.x, it++) {
        const int buf = it & 1;
        const uint32_t uA = uA0 + buf * ABUF_SZ;

        // ---- GEMM: acc[p][msub][nt][4]; cols = p*64 + cn*16; 2 fp16 passes --
        float acc[PP][2][2][4];
#pragma unroll
        for (int p = 0; p < PP; p++)
#pragma unroll
            for (int ms = 0; ms < 2; ms++)
#pragma unroll
                for (int nt = 0; nt < 2; nt++) {
                    acc[p][ms][nt][0] = 0.f; acc[p][ms][nt][1] = 0.f;
                    acc[p][ms][nt][2] = 0.f; acc[p][ms][nt][3] = 0.f;
                }
#pragma unroll
        for (int pass = 0; pass < 2; pass++) {
            uint32_t Bb = (pass == 1) ? uBlo : uBhi;
#pragma unroll
            for (int k = 0; k < 4; k++) {
                uint32_t a0[4], a1[4];
                ldsm_x4(a0, uA + (uint32_t)(arow0 * ASTRIDE + k * 16 + acol0) * 2);
                ldsm_x4(a1, uA + (uint32_t)((arow0 + 16) * ASTRIDE + k * 16 + acol0) * 2);
#pragma unroll
                for (int p = 0; p < PP; p++) {
                    int col = p * 64 + cn * 16;
                    uint32_t b[4];
                    ldsm_x4t(b, Bb + (uint32_t)((k * 16 + brow0) * BSTRIDE +
                                                col + acol0) * 2);
                    mma_f16(acc[p][0][0], a0, b);
                    mma_f16(acc[p][0][1], a0, b + 2);
                    mma_f16(acc[p][1][0], a1, b);
                    mma_f16(acc[p][1][1], a1, b + 2);
                }
            }
        }

        int tn = t + gridDim.x;
        if (tn < NTILES) stageA(tn, buf ^ 1);

        // ---- epilogue: 4 edges/thread, 4 consecutive f -> planar red.v4 ----
        const int f = cn * 16 + 4 * qq;
#pragma unroll
        for (int ms = 0; ms < 2; ms++) {
#pragma unroll
            for (int eidx = 0; eidx < 2; eidx++) {
                int e = t * TILE + em * 32 + ms * 16 + eh + eidx * 8;
                int snd = senders[e], rcv = receivers[e];
                float Yx = Y1[e * 3 + 0], Yy = Y1[e * 3 + 1], Yz = Y1[e * 3 + 2];
                size_t so = (size_t)snd * FF + f;
                float4 ss4 = *(const float4*)(g_s1 + so);
                float4 x4 = *(const float4*)(g_v1x + so);
                float4 y4 = *(const float4*)(g_v1y + so);
                float4 z4 = *(const float4*)(g_v1z + so);
                float ssf[4] = {ss4.x, ss4.y, ss4.z, ss4.w};
                float vx[4] = {x4.x, x4.y, x4.z, x4.w};
                float vy[4] = {y4.x, y4.y, y4.z, y4.w};
                float vz[4] = {z4.x, z4.y, z4.z, z4.w};
                float msv[4], mvx[4], mvy[4], mvz[4];
#pragma unroll
                for (int j = 0; j < 4; j++) {
                    int nt = j >> 1, cb = j & 1;
                    float tw0 = acc[0][ms][nt][eidx * 2 + cb];
                    float tw1 = acc[1][ms][nt][eidx * 2 + cb];
                    float tw2 = acc[2][ms][nt][eidx * 2 + cb];
                    float tw3 = acc[3][ms][nt][eidx * 2 + cb];
                    float tw4 = acc[4][ms][nt][eidx * 2 + cb];
                    float dot = vx[j] * Yx + vy[j] * Yy + vz[j] * Yz;
                    float cx = vy[j] * Yz - vz[j] * Yy;
                    float cy = vz[j] * Yx - vx[j] * Yz;
                    float cz = vx[j] * Yy - vy[j] * Yx;
                    msv[j] = tw0 * ssf[j] + tw1 * dot * INV_SQRT3;
                    float t2s = tw2 * ssf[j];
                    float t4 = tw4 * INV_SQRT2;
                    mvx[j] = t2s * Yx + tw3 * vx[j] + t4 * cx;
                    mvy[j] = t2s * Yy + tw3 * vy[j] + t4 * cy;
                    mvz[j] = t2s * Yz + tw3 * vz[j] + t4 * cz;
                }
                size_t ro = (size_t)rcv * FF + f;
                red4(g_As + ro, msv[0], msv[1], msv[2], msv[3]);
                red4(g_Avx + ro, mvx[0], mvx[1], mvx[2], mvx[3]);
                red4(g_Avy + ro, mvy[0], mvy[1], mvy[2], mvy[3]);
                red4(g_Avz + ro, mvz[0], mvz[1], mvz[2], mvz[3]);
            }
        }
        __syncthreads();
    }
}

// ---------------------------------------------------------------------------
// Kernel C (R15 best + planar accumulator staging): species-binned,
// 8 nodes/iter (2 per thread), W_sc in smem, W_int/W_prod via __ldg broadcast.
// ---------------------------------------------------------------------------
__global__ __launch_bounds__(256) void knodeC(
    const float* __restrict__ s, const float* __restrict__ v,
    const float* __restrict__ W_sc_s, const float* __restrict__ W_sc_v,
    const float* __restrict__ W_int_s, const float* __restrict__ W_int_v,
    const float* __restrict__ w_prod_s, const float* __restrict__ w_prod_v,
    const float* __restrict__ W_prod_s, const float* __restrict__ W_prod_v,
    const float* __restrict__ W_read,
    float* __restrict__ out_node, float* __restrict__ out_s,
    float* __restrict__ out_v)
{
    __shared__ float2 sWsc[FF * FF];
    __shared__ float swps[5 * FF], swpv[4 * FF], sWr[FF];
    __shared__ float4 sAX[8 * FF];
    __shared__ float4 sVX[8 * FF];
    __shared__ float4 sBX[8 * FF];
    __shared__ float sRed[16];
    __shared__ int sNode[8];

    const int sp = blockIdx.x / NBC;
    const int chunk = blockIdx.x % NBC;
    const int cnt = g_cur[sp];
    const int tid = threadIdx.x;

    for (int i = tid; i < FF * FF; i += 256)
        sWsc[i] = make_float2(W_sc_s[sp * FF * FF + i], W_sc_v[sp * FF * FF + i]);
    if (tid < FF) sWr[tid] = W_read[tid];
    for (int i = tid; i < 5 * FF; i += 256) swps[i] = w_prod_s[sp * 5 * FF + i];
    if (tid < 4 * FF) swpv[tid] = w_prod_v[sp * 4 * FF + tid];

    const int* order = g_order + sp * NN;

    for (int gbase = chunk * 8; gbase < cnt; gbase += NBC * 8) {
        __syncthreads();
        if (tid < 8) {
            int idx = gbase + tid;
            sNode[tid] = (idx < cnt) ? order[idx] : -1;
        }
        __syncthreads();
        for (int i = tid; i < 8 * FF; i += 256) {
            int node = sNode[i >> 6];
            if (node < 0) node = sNode[0];
            int f = i & 63;
            size_t o = (size_t)node * FF + f;
            sAX[i] = make_float4(g_Avx[o], g_Avy[o], g_Avz[o], g_As[o]);
            const float* vvp = v + (size_t)node * FF * 3 + f * 3;
            sVX[i] = make_float4(vvp[0], vvp[1], vvp[2], s[o]);
        }
        __syncthreads();

        int nl = tid >> 6, g = tid & 63;
        int n0 = sNode[nl], n1 = sNode[nl + 4];
        const float4* pA0 = sAX + nl * FF;
        const float4* pX0 = sVX + nl * FF;
        const float4* pA1 = sAX + (nl + 4) * FF;
        const float4* pX1 = sVX + (nl + 4) * FF;

        float as0 = 0.f, ax0 = 0.f, ay0 = 0.f, az0 = 0.f;
        float cs0 = 0.f, cx0 = 0.f, cy0 = 0.f, cz0 = 0.f;
        float as1 = 0.f, ax1 = 0.f, ay1 = 0.f, az1 = 0.f;
        float cs1 = 0.f, cx1 = 0.f, cy1 = 0.f, cz1 = 0.f;
#pragma unroll 4
        for (int f = 0; f < FF; f++) {
            float wis = __ldg(W_int_s + f * FF + g);
            float wiv = __ldg(W_int_v + f * FF + g);
            float2 wsc = sWsc[f * FF + g];
            float4 a0 = pA0[f], x0 = pX0[f];
            float4 a1 = pA1[f], x1 = pX1[f];
            as0 += a0.w * wis;
            ax0 += a0.x * wiv; ay0 += a0.y * wiv; az0 += a0.z * wiv;
            cs0 += x0.w * wsc.x;
            cx0 += x0.x * wsc.y; cy0 += x0.y * wsc.y; cz0 += x0.z * wsc.y;
            as1 += a1.w * wis;
            ax1 += a1.x * wiv; ay1 += a1.y * wiv; az1 += a1.z * wiv;
            cs1 += x1.w * wsc.x;
            cx1 += x1.x * wsc.y; cy1 += x1.y * wsc.y; cz1 += x1.z * wsc.y;
        }
        const float inv = 0.25f;
        as0 *= inv; ax0 *= inv; ay0 *= inv; az0 *= inv;
        as1 *= inv; ax1 *= inv; ay1 *= inv; az1 *= inv;

        float w0 = swps[0 * FF + g], w1 = swps[1 * FF + g], w2 = swps[2 * FF + g];
        float w3 = swps[3 * FF + g], w4 = swps[4 * FF + g];
        float u0 = swpv[0 * FF + g], u1 = swpv[1 * FF + g];
        float u2 = swpv[2 * FF + g], u3 = swpv[3 * FF + g];
        {
            float d = ax0 * ax0 + ay0 * ay0 + az0 * az0;
            float a2 = as0 * as0;
            float Bs = w0 * as0 + w1 * a2 + w2 * d + w3 * a2 * as0 + w4 * as0 * d;
            float gv = u0 + u1 * as0 + u2 * a2 + u3 * d;
            sBX[nl * FF + g] = make_float4(gv * ax0, gv * ay0, gv * az0, Bs);
        }
        {
            float d = ax1 * ax1 + ay1 * ay1 + az1 * az1;
            float a2 = as1 * as1;
            float Bs = w0 * as1 + w1 * a2 + w2 * d + w3 * a2 * as1 + w4 * as1 * d;
            float gv = u0 + u1 * as1 + u2 * a2 + u3 * d;
            sBX[(nl + 4) * FF + g] = make_float4(gv * ax1, gv * ay1, gv * az1, Bs);
        }
        __syncthreads();

        const float4* pB0 = sBX + nl * FF;
        const float4* pB1 = sBX + (nl + 4) * FF;
        float so0 = cs0, vx0 = cx0, vy0 = cy0, vz0 = cz0;
        float so1 = cs1, vx1 = cx1, vy1 = cy1, vz1 = cz1;
#pragma unroll 4
        for (int f = 0; f < FF; f++) {
            float wp = __ldg(W_prod_s + f * FF + g);
            float wv = __ldg(W_prod_v + f * FF + g);
            float4 b0 = pB0[f], b1 = pB1[f];
            so0 += b0.w * wp;
            vx0 += b0.x * wv; vy0 += b0.y * wv; vz0 += b0.z * wv;
            so1 += b1.w * wp;
            vx1 += b1.x * wv; vy1 += b1.y * wv; vz1 += b1.z * wv;
        }
        if (n0 >= 0) {
            out_s[n0 * FF + g] = so0;
            out_v[n0 * FF * 3 + g * 3 + 0] = vx0;
            out_v[n0 * FF * 3 + g * 3 + 1] = vy0;
            out_v[n0 * FF * 3 + g * 3 + 2] = vz0;
        }
        if (n1 >= 0) {
            out_s[n1 * FF + g] = so1;
            out_v[n1 * FF * 3 + g * 3 + 0] = vx1;
            out_v[n1 * FF * 3 + g * 3 + 1] = vy1;
            out_v[n1 * FF * 3 + g * 3 + 2] = vz1;
        }

        float r0 = so0 * sWr[g];
        float r1 = so1 * sWr[g];
#pragma unroll
        for (int o = 16; o > 0; o >>= 1) {
            r0 += __shfl_down_sync(0xffffffffu, r0, o);
            r1 += __shfl_down_sync(0xffffffffu, r1, o);
        }
        int w = tid >> 5;
        if ((tid & 31) == 0) { sRed[w * 2] = r0; sRed[w * 2 + 1] = r1; }
        __syncthreads();
        if (tid < 8) {
            int base = (tid & 3) * 4;
            if (tid < 4) {
                int n = sNode[tid];
                if (n >= 0) out_node[n] = sRed[base] + sRed[base + 2];
            } else {
                int n = sNode[(tid & 3) + 4];
                if (n >= 0) out_node[n] = sRed[base + 1] + sRed[base + 3];
            }
        }
    }
}

// ---------------------------------------------------------------------------
extern "C" void kernel_launch(void* const* d_in, const int* in_sizes, int n_in,
                              void* d_out, int out_size)
{
    const float* s    = (const float*)d_in[0];
    const float* v    = (const float*)d_in[1];
    const float* Y1   = (const float*)d_in[2];
    const float* ef   = (const float*)d_in[3];
    const int*   spec = (const int*)d_in[4];
    const int*   snd  = (const int*)d_in[5];
    const int*   rcv  = (const int*)d_in[6];
    const float* Wls  = (const float*)d_in[7];
    const float* Wlv  = (const float*)d_in[8];
    const float* Wscs = (const float*)d_in[9];
    const float* Wscv = (const float*)d_in[10];
    const float* Wr1  = (const float*)d_in[11];
    const float* Wr2  = (const float*)d_in[12];
    const float* Wis  = (const float*)d_in[13];
    const float* Wiv  = (const float*)d_in[14];
    const float* wps  = (const float*)d_in[15];
    const float* wpv  = (const float*)d_in[16];
    const float* Wps  = (const float*)d_in[17];
    const float* Wpv  = (const float*)d_in[18];
    const float* Wrd  = (const float*)d_in[19];

    float* out = (float*)d_out;
    float* out_node = out;
    float* out_s = out + NN;
    float* out_v = out + NN + NN * FF;

    cudaFuncSetAttribute(kedge9, cudaFuncAttributeMaxDynamicSharedMemorySize, DYN_BYTES);

    kreset<<<1, 32>>>();
    knodeA<<<592, 256>>>(s, v, spec, Wls, Wlv);
    kedge9<<<152, 256, DYN_BYTES>>>(Y1, ef, snd, rcv, Wr1, Wr2);
    knodeC<<<SS * NBC, 256>>>(s, v, Wscs, Wscv, Wis, Wiv,
                              wps, wpv, Wps, Wpv, Wrd,
                              out_node, out_s, out_v);
}